// round 5
// baseline (speedup 1.0000x reference)
#include <cuda_runtime.h>
#include <math.h>

// Problem dims (fixed)
#define BATCH 4
#define SEQ   2048
#define DIN   1024
#define HID   1024

// Scratch (allocation-free: __device__ globals)
__device__ float g_Q[(long)BATCH * SEQ * HID];
__device__ float g_K[(long)BATCH * SEQ * HID];
__device__ float g_V[(long)BATCH * SEQ * HID];
__device__ float g_S[(long)BATCH * SEQ * SEQ];

// ---------------- Tiled fp32 GEMM ----------------
// C[M,N] = alpha * A[M,K] @ op(B) + bias   (op(B)=B [K,N] row-major if !TRANSB,
//                                           op(B)=B^T with B [N,K] row-major if TRANSB)
// M,N multiples of 128; K multiple of 16. 256 threads, 8x8 microtile, BK=16.
#define BM 128
#define BN 128
#define BK 16
#define TM 8
#define TN 8

template<bool TRANSB, bool HAS_BIAS>
__global__ __launch_bounds__(256) void gemm_kernel(
    const float* __restrict__ A, const float* __restrict__ B,
    const float* __restrict__ bias, float* __restrict__ C,
    int M, int N, int K,
    long strideA, long strideB, long strideC, float alpha)
{
    const int bz = blockIdx.z;
    A += bz * strideA;
    B += bz * strideB;
    C += bz * strideC;

    __shared__ float As[BK][BM];   // 16 x 128 = 8 KB
    __shared__ float Bs[BK][BN];   // 16 x 128 = 8 KB

    const int tid = threadIdx.x;
    const int tx = tid & 15;     // 0..15 -> col groups
    const int ty = tid >> 4;     // 0..15 -> row groups

    const int rowBase = blockIdx.y * BM;
    const int colBase = blockIdx.x * BN;

    float acc[TM][TN];
#pragma unroll
    for (int i = 0; i < TM; i++)
#pragma unroll
        for (int j = 0; j < TN; j++) acc[i][j] = 0.f;

    for (int k0 = 0; k0 < K; k0 += BK) {
        // ---- A tile: 128 rows x 16 k-cols = 512 float4; 2 per thread ----
#pragma unroll
        for (int p = 0; p < 2; p++) {
            const int l   = tid + p * 256;
            const int row = l >> 2;          // 0..127
            const int col = (l & 3) * 4;     // 0,4,8,12
            float4 av = *reinterpret_cast<const float4*>(
                &A[(long)(rowBase + row) * K + k0 + col]);
            As[col + 0][row] = av.x;
            As[col + 1][row] = av.y;
            As[col + 2][row] = av.z;
            As[col + 3][row] = av.w;
        }
        // ---- B tile ----
        if (TRANSB) {
            // B is [N,K] row-major: rows = n (128), cols = k (16); same as A pattern
#pragma unroll
            for (int p = 0; p < 2; p++) {
                const int l   = tid + p * 256;
                const int row = l >> 2;          // n offset 0..127
                const int col = (l & 3) * 4;     // k offset
                float4 bv = *reinterpret_cast<const float4*>(
                    &B[(long)(colBase + row) * K + k0 + col]);
                Bs[col + 0][row] = bv.x;
                Bs[col + 1][row] = bv.y;
                Bs[col + 2][row] = bv.z;
                Bs[col + 3][row] = bv.w;
            }
        } else {
            // B is [K,N] row-major: 16 k-rows x 128 n-cols = 512 float4; coalesced rows
#pragma unroll
            for (int p = 0; p < 2; p++) {
                const int l   = tid + p * 256;
                const int row = l >> 5;          // k offset 0..15
                const int col = (l & 31) * 4;    // n offset 0..124
                float4 bv = *reinterpret_cast<const float4*>(
                    &B[(long)(k0 + row) * N + colBase + col]);
                *reinterpret_cast<float4*>(&Bs[row][col]) = bv;
            }
        }
        __syncthreads();

#pragma unroll
        for (int kk = 0; kk < BK; kk++) {
            float ra[TM], rb[TN];
#pragma unroll
            for (int i = 0; i < TM; i++) ra[i] = As[kk][ty * TM + i];
#pragma unroll
            for (int j = 0; j < TN; j++) rb[j] = Bs[kk][tx * TN + j];
#pragma unroll
            for (int i = 0; i < TM; i++)
#pragma unroll
                for (int j = 0; j < TN; j++)
                    acc[i][j] = fmaf(ra[i], rb[j], acc[i][j]);
        }
        __syncthreads();
    }

#pragma unroll
    for (int i = 0; i < TM; i++) {
        const long row = rowBase + ty * TM + i;
#pragma unroll
        for (int j = 0; j < TN; j += 4) {
            const int col = colBase + tx * TN + j;
            float4 v;
            v.x = acc[i][j + 0] * alpha;
            v.y = acc[i][j + 1] * alpha;
            v.z = acc[i][j + 2] * alpha;
            v.w = acc[i][j + 3] * alpha;
            if (HAS_BIAS) {
                v.x += bias[col + 0];
                v.y += bias[col + 1];
                v.z += bias[col + 2];
                v.w += bias[col + 3];
            }
            *reinterpret_cast<float4*>(&C[row * N + col]) = v;
        }
    }
}

// ---------------- Row softmax over SEQ=2048 ----------------
__global__ __launch_bounds__(256) void softmax_kernel(float* __restrict__ S)
{
    const long row = blockIdx.x;
    float* p = S + row * SEQ;
    const int tid = threadIdx.x;
    const int lane = tid & 31, warp = tid >> 5;
    __shared__ float sh[8];

    float vals[SEQ / 256];
    float m = -INFINITY;
#pragma unroll
    for (int i = 0; i < SEQ / 256; i++) {
        vals[i] = p[i * 256 + tid];
        m = fmaxf(m, vals[i]);
    }
#pragma unroll
    for (int o = 16; o > 0; o >>= 1) m = fmaxf(m, __shfl_xor_sync(0xffffffffu, m, o));
    if (lane == 0) sh[warp] = m;
    __syncthreads();
    m = sh[0];
#pragma unroll
    for (int w = 1; w < 8; w++) m = fmaxf(m, sh[w]);
    __syncthreads();

    float sum = 0.f;
#pragma unroll
    for (int i = 0; i < SEQ / 256; i++) {
        vals[i] = __expf(vals[i] - m);
        sum += vals[i];
    }
#pragma unroll
    for (int o = 16; o > 0; o >>= 1) sum += __shfl_xor_sync(0xffffffffu, sum, o);
    if (lane == 0) sh[warp] = sum;
    __syncthreads();
    sum = sh[0];
#pragma unroll
    for (int w = 1; w < 8; w++) sum += sh[w];

    const float inv = 1.0f / sum;
#pragma unroll
    for (int i = 0; i < SEQ / 256; i++) p[i * 256 + tid] = vals[i] * inv;
}

// ---------------- launch ----------------
extern "C" void kernel_launch(void* const* d_in, const int* in_sizes, int n_in,
                              void* d_out, int out_size)
{
    const float* x  = (const float*)d_in[0];
    const float* Wq = (const float*)d_in[1];
    const float* bq = (const float*)d_in[2];
    const float* Wk = (const float*)d_in[3];
    const float* bk = (const float*)d_in[4];
    const float* Wv = (const float*)d_in[5];
    const float* bv = (const float*)d_in[6];
    float* out = (float*)d_out;

    float *qP, *kP, *vP, *sP;
    cudaGetSymbolAddress((void**)&qP, g_Q);
    cudaGetSymbolAddress((void**)&kP, g_K);
    cudaGetSymbolAddress((void**)&vP, g_V);
    cudaGetSymbolAddress((void**)&sP, g_S);

    const int M_qkv = BATCH * SEQ;                 // 8192
    const long sQ = (long)SEQ * HID;               // per-batch Q/K/V stride
    const long sS = (long)SEQ * SEQ;               // per-batch scores stride
    const float inv_dk = 1.0f / sqrtf((float)HID); // 1/32

    dim3 blk(256);
    // 1-3) QKV projections: [8192,1024] = x @ W + b
    {
        dim3 grd(HID / BN, M_qkv / BM, 1);
        gemm_kernel<false, true><<<grd, blk>>>(x, Wq, bq, qP, M_qkv, HID, DIN, 0, 0, 0, 1.0f);
        gemm_kernel<false, true><<<grd, blk>>>(x, Wk, bk, kP, M_qkv, HID, DIN, 0, 0, 0, 1.0f);
        gemm_kernel<false, true><<<grd, blk>>>(x, Wv, bv, vP, M_qkv, HID, DIN, 0, 0, 0, 1.0f);
    }
    // 4) scores = Q @ K^T / sqrt(H), batched over BATCH
    {
        dim3 grd(SEQ / BN, SEQ / BM, BATCH);
        gemm_kernel<true, false><<<grd, blk>>>(qP, kP, nullptr, sP, SEQ, SEQ, HID, sQ, sQ, sS, inv_dk);
    }
    // 5) softmax rows
    softmax_kernel<<<BATCH * SEQ, blk>>>(sP);
    // 6) out = P @ V, batched
    {
        dim3 grd(HID / BN, SEQ / BM, BATCH);
        gemm_kernel<false, false><<<grd, blk>>>(sP, vP, nullptr, out, SEQ, HID, SEQ, sS, sQ, sQ, 1.0f);
    }
    (void)in_sizes; (void)n_in; (void)out_size;
}

// round 17
// speedup vs baseline: 5.0682x; 5.0682x over previous
#include <cuda_runtime.h>
#include <cuda_fp16.h>
#include <stdint.h>
#include <math.h>

// ---------------- Problem dims (fixed) ----------------
#define BATCH 4
#define SEQ   2048
#define DIN   1024
#define HID   1024
#define MQKV  (BATCH*SEQ)   // 8192

#define NEL_X   ((long)MQKV*DIN)
#define NEL_W   ((long)DIN*HID)
#define NEL_QKV ((long)MQKV*HID)
#define NEL_S   ((long)BATCH*SEQ*SEQ)

// ---------------- Scratch (allocation-free device globals) ----------------
__device__ __half g_xh[NEL_X];
__device__ __half g_Wqt[NEL_W], g_Wkt[NEL_W], g_Wvt[NEL_W];   // W^T [H, D] fp16
__device__ __half g_Qh[NEL_QKV], g_Kh[NEL_QKV], g_Vh[NEL_QKV];
__device__ __half g_Vt[NEL_QKV];                               // V^T per batch [HID, SEQ]
__device__ float  g_Sf[NEL_S];
__device__ __half g_Ph[NEL_S];

// ---------------- helpers ----------------
__device__ __forceinline__ uint32_t smem_u32(const void* p) {
    uint32_t a;
    asm("{ .reg .u64 t; cvta.to.shared.u64 t, %1; cvt.u32.u64 %0, t; }" : "=r"(a) : "l"(p));
    return a;
}

// ---------------- fp16 tensor-core GEMM (mma.sync, sm_80-class path) ----------------
// D[m,n] = alpha * sum_k A[m,k]*B[n,k] (+bias[n]); A:[M,K] fp16 row-major,
// B:[N,K] fp16 row-major (i.e. op(B)=B^T), C: OutT (float or __half).
// Tile 128x128xBK32, 8 warps (2x4), warp tile 64x32 of m16n8k16.
#define BKH 32
#define PAD 40   // halves per smem row (80 B: 16B-aligned, conflict-free frags)

template<typename OutT, bool HAS_BIAS>
__global__ __launch_bounds__(256)
void hgemm_kernel(const __half* __restrict__ A, const __half* __restrict__ B,
                  const float* __restrict__ bias, OutT* __restrict__ C,
                  int K, int N, long sA, long sB, long sC, float alpha)
{
    __shared__ __half SM[2][2][128 * PAD];   // [stage][A/B] : 40960 B total

    const int tid  = threadIdx.x;
    const int lane = tid & 31, wid = tid >> 5;
    const int wm = wid >> 2, wn = wid & 3;       // warps: 2 (M) x 4 (N)
    const int gid = lane >> 2, tig = lane & 3;   // mma octet layout
    const int bz = blockIdx.z;
    A += bz * sA; B += bz * sB; C += bz * sC;
    const long aRow0 = (long)blockIdx.y * 128;
    const long bRow0 = (long)blockIdx.x * 128;

    float acc[4][4][4];
#pragma unroll
    for (int mi = 0; mi < 4; mi++)
#pragma unroll
        for (int ni = 0; ni < 4; ni++)
#pragma unroll
            for (int c = 0; c < 4; c++) acc[mi][ni][c] = 0.f;

    // per-thread cp.async mapping: 2 chunks of A + 2 of B per stage (16 B each)
    const int ldRow0 = tid >> 2;          // 0..63
    const int ldCw   = tid & 3;           // 16B chunk in row (k offset = cw*8)

    const int KT = K / BKH;

    auto issue_stage = [&](int kt, int s) {
        const int k0 = kt * BKH;
#pragma unroll
        for (int p = 0; p < 2; p++) {
            const int row = ldRow0 + p * 64;
            const long ka = (aRow0 + row) * (long)K + k0 + ldCw * 8;
            const long kb = (bRow0 + row) * (long)K + k0 + ldCw * 8;
            const uint32_t sa = smem_u32(&SM[s][0][row * PAD + ldCw * 8]);
            const uint32_t sb = smem_u32(&SM[s][1][row * PAD + ldCw * 8]);
            asm volatile("cp.async.cg.shared.global [%0], [%1], 16;" :: "r"(sa), "l"(A + ka));
            asm volatile("cp.async.cg.shared.global [%0], [%1], 16;" :: "r"(sb), "l"(B + kb));
        }
        asm volatile("cp.async.commit_group;" ::: "memory");
    };

    issue_stage(0, 0);
    for (int kt = 0; kt < KT; kt++) {
        const int s = kt & 1;
        if (kt + 1 < KT) {
            issue_stage(kt + 1, s ^ 1);
            asm volatile("cp.async.wait_group 1;" ::: "memory");
        } else {
            asm volatile("cp.async.wait_group 0;" ::: "memory");
        }
        __syncthreads();

#pragma unroll
        for (int ks = 0; ks < 2; ks++) {
            const int kb = ks * 16 + tig * 2;
            uint32_t af[4][4], bf[4][2];
#pragma unroll
            for (int mi = 0; mi < 4; mi++) {
                const int r = wm * 64 + mi * 16 + gid;
                const __half* pa = &SM[s][0][r * PAD + kb];
                af[mi][0] = *(const uint32_t*)(pa);
                af[mi][1] = *(const uint32_t*)(pa + 8 * PAD);
                af[mi][2] = *(const uint32_t*)(pa + 8);
                af[mi][3] = *(const uint32_t*)(pa + 8 * PAD + 8);
            }
#pragma unroll
            for (int ni = 0; ni < 4; ni++) {
                const int r = wn * 32 + ni * 8 + gid;
                const __half* pb = &SM[s][1][r * PAD + kb];
                bf[ni][0] = *(const uint32_t*)(pb);
                bf[ni][1] = *(const uint32_t*)(pb + 8);
            }
#pragma unroll
            for (int mi = 0; mi < 4; mi++)
#pragma unroll
                for (int ni = 0; ni < 4; ni++)
                    asm volatile(
                        "mma.sync.aligned.m16n8k16.row.col.f32.f16.f16.f32 "
                        "{%0,%1,%2,%3}, {%4,%5,%6,%7}, {%8,%9}, {%0,%1,%2,%3};"
                        : "+f"(acc[mi][ni][0]), "+f"(acc[mi][ni][1]),
                          "+f"(acc[mi][ni][2]), "+f"(acc[mi][ni][3])
                        : "r"(af[mi][0]), "r"(af[mi][1]), "r"(af[mi][2]), "r"(af[mi][3]),
                          "r"(bf[ni][0]), "r"(bf[ni][1]));
        }
        __syncthreads();
    }

    // epilogue
#pragma unroll
    for (int mi = 0; mi < 4; mi++) {
#pragma unroll
        for (int ni = 0; ni < 4; ni++) {
            const long row = aRow0 + wm * 64 + mi * 16 + gid;
            const long col = bRow0 + wn * 32 + ni * 8 + tig * 2;
            float v0 = acc[mi][ni][0] * alpha, v1 = acc[mi][ni][1] * alpha;
            float v2 = acc[mi][ni][2] * alpha, v3 = acc[mi][ni][3] * alpha;
            if (HAS_BIAS) {
                const float b0 = bias[col], b1 = bias[col + 1];
                v0 += b0; v1 += b1; v2 += b0; v3 += b1;
            }
            if (sizeof(OutT) == 4) {
                *(float2*)((float*)C + row * N + col)       = make_float2(v0, v1);
                *(float2*)((float*)C + (row + 8) * N + col) = make_float2(v2, v3);
            } else {
                *(__half2*)((__half*)C + row * N + col)       = __floats2half2_rn(v0, v1);
                *(__half2*)((__half*)C + (row + 8) * N + col) = __floats2half2_rn(v2, v3);
            }
        }
    }
}

// ---------------- fp32 -> fp16 elementwise ----------------
__global__ __launch_bounds__(256) void f2h_kernel(const float* __restrict__ in,
                                                  __half* __restrict__ out)
{
    const long i = ((long)blockIdx.x * 256 + threadIdx.x) * 4;
    const float4 v = *(const float4*)(in + i);
    *(__half2*)(out + i)     = __floats2half2_rn(v.x, v.y);
    *(__half2*)(out + i + 2) = __floats2half2_rn(v.z, v.w);
}

// ---------------- transpose [R,C] -> fp16 [C,R] ----------------
template<typename InT>
__global__ __launch_bounds__(256) void transpose_h_kernel(
    const InT* __restrict__ in, __half* __restrict__ out, int R, int C, long sIn, long sOut)
{
    __shared__ float t[32][33];
    in  += (long)blockIdx.z * sIn;
    out += (long)blockIdx.z * sOut;
    const int c0 = blockIdx.x * 32, r0 = blockIdx.y * 32;
    const int tx = threadIdx.x, ty = threadIdx.y;
#pragma unroll
    for (int i = ty; i < 32; i += 8)
        t[i][tx] = (float)in[(long)(r0 + i) * C + c0 + tx];
    __syncthreads();
#pragma unroll
    for (int i = ty; i < 32; i += 8)
        out[(long)(c0 + i) * R + r0 + tx] = __float2half(t[tx][i]);
}

// ---------------- softmax rows of 2048: fp32 in -> fp16 probs ----------------
__global__ __launch_bounds__(256) void softmax_h_kernel(
    const float* __restrict__ S, __half* __restrict__ P)
{
    const long row = blockIdx.x;
    const float* p = S + row * SEQ;
    const int tid = threadIdx.x, lane = tid & 31, warp = tid >> 5;
    __shared__ float sh[8];

    float vals[SEQ / 256];
    float m = -INFINITY;
#pragma unroll
    for (int i = 0; i < SEQ / 256; i++) {
        vals[i] = p[i * 256 + tid];
        m = fmaxf(m, vals[i]);
    }
#pragma unroll
    for (int o = 16; o > 0; o >>= 1) m = fmaxf(m, __shfl_xor_sync(0xffffffffu, m, o));
    if (lane == 0) sh[warp] = m;
    __syncthreads();
    m = sh[0];
#pragma unroll
    for (int w = 1; w < 8; w++) m = fmaxf(m, sh[w]);
    __syncthreads();

    float sum = 0.f;
#pragma unroll
    for (int i = 0; i < SEQ / 256; i++) {
        vals[i] = __expf(vals[i] - m);
        sum += vals[i];
    }
#pragma unroll
    for (int o = 16; o > 0; o >>= 1) sum += __shfl_xor_sync(0xffffffffu, sum, o);
    if (lane == 0) sh[warp] = sum;
    __syncthreads();
    sum = sh[0];
#pragma unroll
    for (int w = 1; w < 8; w++) sum += sh[w];

    const float inv = 1.0f / sum;
#pragma unroll
    for (int i = 0; i < SEQ / 256; i++)
        P[row * SEQ + i * 256 + tid] = __float2half(vals[i] * inv);
}

// ---------------- launch ----------------
#define SYM(ptr, sym) cudaGetSymbolAddress((void**)&ptr, sym)

extern "C" void kernel_launch(void* const* d_in, const int* in_sizes, int n_in,
                              void* d_out, int out_size)
{
    const float* x  = (const float*)d_in[0];
    const float* Wq = (const float*)d_in[1];
    const float* bq = (const float*)d_in[2];
    const float* Wk = (const float*)d_in[3];
    const float* bk = (const float*)d_in[4];
    const float* Wv = (const float*)d_in[5];
    const float* bv = (const float*)d_in[6];
    float* out = (float*)d_out;

    __half *xh, *Wqt, *Wkt, *Wvt, *Qh, *Kh, *Vh, *Vt, *Ph;
    float *Sf;
    SYM(xh, g_xh);
    SYM(Wqt, g_Wqt); SYM(Wkt, g_Wkt); SYM(Wvt, g_Wvt);
    SYM(Qh, g_Qh); SYM(Kh, g_Kh); SYM(Vh, g_Vh); SYM(Vt, g_Vt);
    SYM(Sf, g_Sf); SYM(Ph, g_Ph);

    const long sQ = (long)SEQ * HID;
    const long sS = (long)SEQ * SEQ;
    const float inv_dk = 1.0f / 32.0f;   // 1/sqrt(HID)

    // 0) x -> fp16; W -> W^T fp16
    f2h_kernel<<<NEL_X / 1024, 256>>>(x, xh);
    {
        dim3 g(HID / 32, DIN / 32, 1), b(32, 8);
        transpose_h_kernel<float><<<g, b>>>(Wq, Wqt, DIN, HID, 0, 0);
        transpose_h_kernel<float><<<g, b>>>(Wk, Wkt, DIN, HID, 0, 0);
        transpose_h_kernel<float><<<g, b>>>(Wv, Wvt, DIN, HID, 0, 0);
    }
    // 1) QKV projections -> fp16 directly
    {
        dim3 g(HID / 128, MQKV / 128, 1);
        hgemm_kernel<__half, true><<<g, 256>>>(xh, Wqt, bq, Qh, DIN, HID, 0, 0, 0, 1.0f);
        hgemm_kernel<__half, true><<<g, 256>>>(xh, Wkt, bk, Kh, DIN, HID, 0, 0, 0, 1.0f);
        hgemm_kernel<__half, true><<<g, 256>>>(xh, Wvt, bv, Vh, DIN, HID, 0, 0, 0, 1.0f);
    }
    // 2) V^T per batch: [SEQ,HID] -> [HID,SEQ]
    {
        dim3 g(HID / 32, SEQ / 32, BATCH), b(32, 8);
        transpose_h_kernel<__half><<<g, b>>>(Vh, Vt, SEQ, HID, sQ, sQ);
    }
    // 3) scores = Q @ K^T / 32 (batched) -> fp32
    {
        dim3 g(SEQ / 128, SEQ / 128, BATCH);
        hgemm_kernel<float, false><<<g, 256>>>(Qh, Kh, nullptr, Sf, HID, SEQ, sQ, sQ, sS, inv_dk);
    }
    // 4) softmax -> fp16 probs
    softmax_h_kernel<<<BATCH * SEQ, 256>>>(Sf, Ph);
    // 5) out = P @ V (batched; B = V^T [HID,SEQ]) -> fp32 d_out
    {
        dim3 g(HID / 128, SEQ / 128, BATCH);
        hgemm_kernel<float, false><<<g, 256>>>(Ph, Vt, nullptr, out, SEQ, HID, sS, sQ, sQ, 1.0f);
    }
    (void)in_sizes; (void)n_in; (void)out_size;
}